// round 2
// baseline (speedup 1.0000x reference)
#include <cuda_runtime.h>

#define BATCH 512
#define INF   512
#define OUTF  64
#define KDIM  8
#define ROWW  (INF + OUTF)   // 576

// Scratch: M in [o][i][k] layout so the pairwise kernel reads one contiguous
// 16KB slab per output feature. 1 MB total. (__device__ global: no allocation.)
__device__ float g_M[OUTF * BATCH * KDIM];

// ---------------------------------------------------------------------------
// GEMM: C[i][c] = sum_in x[i][in] * T[in][c]  (T viewed as [512][512] row-major)
// Tile BM=64, BN=32, BK=16; 128 threads; grid (16,8)=128 blocks.
// Epilogue scatters into g_M[o][i][k] with o=c>>3, k=c&7.
// ---------------------------------------------------------------------------
__global__ void gemm_kernel(const float* __restrict__ A, const float* __restrict__ Bm) {
    __shared__ float As[16][64];   // [k][row]
    __shared__ float Bs[16][32];   // [k][col]
    const int tid = threadIdx.x;
    const int tx = tid & 7;        // 0..7   -> 4 cols each
    const int ty = tid >> 3;       // 0..15  -> 4 rows each
    const int rowBase = blockIdx.y * 64;
    const int colBase = blockIdx.x * 32;

    float acc[4][4] = {};

    for (int kt = 0; kt < INF; kt += 16) {
        // A tile: 64 rows x 16 k = 256 float4 loads (2 per thread), transpose to As[k][r]
        #pragma unroll
        for (int l = 0; l < 2; l++) {
            int f  = tid + l * 128;
            int r  = f >> 2;
            int cg = (f & 3) * 4;
            float4 v = *(const float4*)&A[(rowBase + r) * INF + kt + cg];
            As[cg + 0][r] = v.x; As[cg + 1][r] = v.y;
            As[cg + 2][r] = v.z; As[cg + 3][r] = v.w;
        }
        // B tile: 16 k x 32 cols = 128 float4 (1 per thread)
        {
            int kr = tid >> 3;
            int cg = (tid & 7) * 4;
            *(float4*)&Bs[kr][cg] =
                *(const float4*)&Bm[(kt + kr) * (OUTF * KDIM) + colBase + cg];
        }
        __syncthreads();

        #pragma unroll
        for (int k = 0; k < 16; k++) {
            float4 a = *(const float4*)&As[k][ty * 4];
            float4 b = *(const float4*)&Bs[k][tx * 4];
            float av[4] = {a.x, a.y, a.z, a.w};
            float bv[4] = {b.x, b.y, b.z, b.w};
            #pragma unroll
            for (int m = 0; m < 4; m++)
                #pragma unroll
                for (int n = 0; n < 4; n++)
                    acc[m][n] += av[m] * bv[n];
        }
        __syncthreads();
    }

    #pragma unroll
    for (int m = 0; m < 4; m++) {
        int row = rowBase + ty * 4 + m;
        #pragma unroll
        for (int n = 0; n < 4; n++) {
            int col = colBase + tx * 4 + n;
            g_M[(((col >> 3) * BATCH) + row) * KDIM + (col & 7)] = acc[m][n];
        }
    }
}

// ---------------------------------------------------------------------------
// Pairwise: out[i, 512+o] = sum_j exp(-sum_k |M[o][i][k]-M[o][j][k]|)
// grid (64 o, 8 i-chunks), 64 threads: thread -> one i. Full M[o] slab (16KB)
// lives in smem; every j-row read is a warp broadcast (conflict-free).
// ---------------------------------------------------------------------------
__global__ void pairwise_kernel(float* __restrict__ out) {
    __shared__ float4 sm[BATCH * 2];            // 512 rows x 8 floats
    const int o = blockIdx.x;
    const float4* Mo = (const float4*)&g_M[o * BATCH * KDIM];
    for (int t = threadIdx.x; t < BATCH * 2; t += blockDim.x)
        sm[t] = Mo[t];
    __syncthreads();

    const int i = blockIdx.y * blockDim.x + threadIdx.x;
    const float4 a0 = sm[i * 2 + 0];
    const float4 a1 = sm[i * 2 + 1];

    float s0 = 0.f, s1 = 0.f;
    #pragma unroll 2
    for (int j = 0; j < BATCH; j += 2) {
        {
            float4 b0 = sm[j * 2 + 0];
            float4 b1 = sm[j * 2 + 1];
            float d = ( (fabsf(a0.x - b0.x) + fabsf(a0.y - b0.y))
                      + (fabsf(a0.z - b0.z) + fabsf(a0.w - b0.w)) )
                    + ( (fabsf(a1.x - b1.x) + fabsf(a1.y - b1.y))
                      + (fabsf(a1.z - b1.z) + fabsf(a1.w - b1.w)) );
            s0 += __expf(-d);
        }
        {
            float4 b0 = sm[(j + 1) * 2 + 0];
            float4 b1 = sm[(j + 1) * 2 + 1];
            float d = ( (fabsf(a0.x - b0.x) + fabsf(a0.y - b0.y))
                      + (fabsf(a0.z - b0.z) + fabsf(a0.w - b0.w)) )
                    + ( (fabsf(a1.x - b1.x) + fabsf(a1.y - b1.y))
                      + (fabsf(a1.z - b1.z) + fabsf(a1.w - b1.w)) );
            s1 += __expf(-d);
        }
    }
    out[i * ROWW + INF + o] = s0 + s1;
}

// ---------------------------------------------------------------------------
// Copy x into out[:, :512] (row stride 576 floats; both sides 16B aligned)
// ---------------------------------------------------------------------------
__global__ void copy_kernel(const float* __restrict__ x, float* __restrict__ out) {
    const int i = blockIdx.x;
    ((float4*)(out + i * ROWW))[threadIdx.x] =
        ((const float4*)(x + i * INF))[threadIdx.x];
}

extern "C" void kernel_launch(void* const* d_in, const int* in_sizes, int n_in,
                              void* d_out, int out_size) {
    const float* x = (const float*)d_in[0];   // [512, 512]
    const float* T = (const float*)d_in[1];   // [512, 64, 8] == [512, 512]
    float* out = (float*)d_out;               // [512, 576]

    copy_kernel<<<BATCH, INF / 4>>>(x, out);
    gemm_kernel<<<dim3(16, 8), 128>>>(x, T);
    pairwise_kernel<<<dim3(OUTF, 8), 64>>>(out);
}

// round 3
// speedup vs baseline: 1.0990x; 1.0990x over previous
#include <cuda_runtime.h>

#define BATCH 512
#define INF   512
#define OUTF  64
#define KDIM  8
#define ROWW  (INF + OUTF)   // 576
#define PRUNE_T 16.0f        // skipped pairs have d > 16 -> each < 1.1e-7, total < 5.7e-5

// Scratch (device globals: no allocation).
__device__ float g_M [OUTF * BATCH * KDIM];   // [o][i][k], GEMM output
__device__ float g_Ms[OUTF * BATCH * KDIM];   // [o][i][k], rows sorted by s
__device__ float g_s [OUTF * BATCH];          // sorted row-sums per o
__device__ int   g_perm[OUTF * BATCH];        // sorted order -> original i

// ---------------------------------------------------------------------------
// GEMM: C[i][c] = sum_in x[i][in] * T[in][c], scattered to g_M[o][i][k].
// Also copies x into out[:, :512] (fused; stores hide under compute).
// Tile BM=64, BN=32, BK=16; 128 threads; grid (16,8).
// ---------------------------------------------------------------------------
__global__ void gemm_kernel(const float* __restrict__ A, const float* __restrict__ Bm,
                            float* __restrict__ out) {
    __shared__ float As[16][64];
    __shared__ float Bs[16][32];
    const int tid = threadIdx.x;

    // Fused copy: x (65536 float4) spread over 16384 threads, 4 each.
    {
        const int gt = (blockIdx.y * 16 + blockIdx.x) * 128 + tid;
        #pragma unroll
        for (int t = 0; t < 4; t++) {
            int f = gt + t * 16384;
            int row = f >> 7, col = (f & 127) * 4;
            *(float4*)(out + row * ROWW + col) = *(const float4*)(A + row * INF + col);
        }
    }

    const int tx = tid & 7;
    const int ty = tid >> 3;
    const int rowBase = blockIdx.y * 64;
    const int colBase = blockIdx.x * 32;

    float acc[4][4] = {};

    for (int kt = 0; kt < INF; kt += 16) {
        #pragma unroll
        for (int l = 0; l < 2; l++) {
            int f  = tid + l * 128;
            int r  = f >> 2;
            int cg = (f & 3) * 4;
            float4 v = *(const float4*)&A[(rowBase + r) * INF + kt + cg];
            As[cg + 0][r] = v.x; As[cg + 1][r] = v.y;
            As[cg + 2][r] = v.z; As[cg + 3][r] = v.w;
        }
        {
            int kr = tid >> 3;
            int cg = (tid & 7) * 4;
            *(float4*)&Bs[kr][cg] =
                *(const float4*)&Bm[(kt + kr) * (OUTF * KDIM) + colBase + cg];
        }
        __syncthreads();

        #pragma unroll
        for (int k = 0; k < 16; k++) {
            float4 a = *(const float4*)&As[k][ty * 4];
            float4 b = *(const float4*)&Bs[k][tx * 4];
            float av[4] = {a.x, a.y, a.z, a.w};
            float bv[4] = {b.x, b.y, b.z, b.w};
            #pragma unroll
            for (int m = 0; m < 4; m++)
                #pragma unroll
                for (int n = 0; n < 4; n++)
                    acc[m][n] += av[m] * bv[n];
        }
        __syncthreads();
    }

    #pragma unroll
    for (int m = 0; m < 4; m++) {
        int row = rowBase + ty * 4 + m;
        #pragma unroll
        for (int n = 0; n < 4; n++) {
            int col = colBase + tx * 4 + n;
            g_M[(((col >> 3) * BATCH) + row) * KDIM + (col & 7)] = acc[m][n];
        }
    }
}

// ---------------------------------------------------------------------------
// Per-o: row sums, bitonic sort by sum (ascending), gather slab into sorted
// order. grid = 64 (one block per o), 512 threads.
// ---------------------------------------------------------------------------
__global__ void sort_kernel() {
    __shared__ float key[BATCH];
    __shared__ int   idx[BATCH];
    const int o = blockIdx.x;
    const int tid = threadIdx.x;
    const float4* Mo = (const float4*)&g_M[o * BATCH * KDIM];

    float4 r0 = Mo[tid * 2], r1 = Mo[tid * 2 + 1];
    key[tid] = (r0.x + r0.y) + (r0.z + r0.w) + (r1.x + r1.y) + (r1.z + r1.w);
    idx[tid] = tid;
    __syncthreads();

    for (int k = 2; k <= BATCH; k <<= 1) {
        for (int j = k >> 1; j > 0; j >>= 1) {
            int ixj = tid ^ j;
            if (ixj > tid) {
                bool up = (tid & k) == 0;
                float ka = key[tid], kb = key[ixj];
                if ((ka > kb) == up) {
                    key[tid] = kb; key[ixj] = ka;
                    int t = idx[tid]; idx[tid] = idx[ixj]; idx[ixj] = t;
                }
            }
            __syncthreads();
        }
    }

    g_s[o * BATCH + tid]    = key[tid];
    g_perm[o * BATCH + tid] = idx[tid];

    const int p = idx[tid];
    float4* Mso = (float4*)&g_Ms[o * BATCH * KDIM];
    Mso[tid * 2]     = Mo[p * 2];
    Mso[tid * 2 + 1] = Mo[p * 2 + 1];
}

// ---------------------------------------------------------------------------
// Pairwise with warp-uniform pruning window.
// grid (64 o, 4 chunks) x 128 threads: thread -> one sorted-i.
// Warp's j-window: sorted j with s_j in [s_warpmin - T, s_warpmax + T].
// Everything outside contributes < e^-T per term (rigorous bound).
// ---------------------------------------------------------------------------
__global__ void pairwise_kernel(float* __restrict__ out) {
    __shared__ float4 sm[BATCH * 2];   // sorted slab, 16KB
    __shared__ float  sk[BATCH];       // sorted sums, 2KB
    const int o = blockIdx.x;
    const int tid = threadIdx.x;

    const float4* Ms = (const float4*)&g_Ms[o * BATCH * KDIM];
    for (int t = tid; t < BATCH * 2; t += 128) sm[t] = Ms[t];
    for (int t = tid; t < BATCH; t += 128)     sk[t] = g_s[o * BATCH + t];
    __syncthreads();

    const int i = blockIdx.y * 128 + tid;
    const float4 a0 = sm[i * 2 + 0];
    const float4 a1 = sm[i * 2 + 1];

    // Warp window bounds (warp-uniform binary searches on smem).
    const int wbase = i & ~31;
    const float lo = sk[wbase]      - PRUNE_T;
    const float hi = sk[wbase + 31] + PRUNE_T;
    int jlo, jhi;
    { int l = 0, r = BATCH; while (l < r) { int m = (l + r) >> 1; if (sk[m] <  lo) l = m + 1; else r = m; } jlo = l; }
    { int l = 0, r = BATCH; while (l < r) { int m = (l + r) >> 1; if (sk[m] <= hi) l = m + 1; else r = m; } jhi = l; }

    float s = 0.f;
    #pragma unroll 2
    for (int j = jlo; j < jhi; j++) {
        float4 b0 = sm[j * 2 + 0];
        float4 b1 = sm[j * 2 + 1];
        float d = ( (fabsf(a0.x - b0.x) + fabsf(a0.y - b0.y))
                  + (fabsf(a0.z - b0.z) + fabsf(a0.w - b0.w)) )
                + ( (fabsf(a1.x - b1.x) + fabsf(a1.y - b1.y))
                  + (fabsf(a1.z - b1.z) + fabsf(a1.w - b1.w)) );
        s += __expf(-d);
    }

    const int oi = g_perm[o * BATCH + i];
    out[oi * ROWW + INF + o] = s;
}

extern "C" void kernel_launch(void* const* d_in, const int* in_sizes, int n_in,
                              void* d_out, int out_size) {
    const float* x = (const float*)d_in[0];   // [512, 512]
    const float* T = (const float*)d_in[1];   // [512, 64, 8] == [512, 512]
    float* out = (float*)d_out;               // [512, 576]

    gemm_kernel<<<dim3(16, 8), 128>>>(x, T, out);
    sort_kernel<<<OUTF, BATCH>>>();
    pairwise_kernel<<<dim3(OUTF, 4), 128>>>(out);
}

// round 4
// speedup vs baseline: 1.4793x; 1.3461x over previous
#include <cuda_runtime.h>
#include <cstdint>

#define BATCH 512
#define INF   512
#define OUTF  64
#define KDIM  8
#define ROWW  (INF + OUTF)   // 576
#define PRUNE_T 16.0f        // skipped pairs have d > 16 -> each < 1.1e-7, total < 5.7e-5

// Scratch (device globals: no allocation).
__device__ float g_M [OUTF * BATCH * KDIM];   // [o][i][k], GEMM output
__device__ float g_Ms[OUTF * BATCH * KDIM];   // [o][i][k], rows sorted by s
__device__ float g_s [OUTF * BATCH];          // sorted row-sums per o
__device__ int   g_perm[OUTF * BATCH];        // sorted order -> original i

// ---------------------------------------------------------------------------
// tf32 tensor-core GEMM: C[i][c] = sum_in x[i][in] * T[in][c]
// BM=64, BN=32, BK=32; 128 threads (4 warps); grid (16,8) = 128 blocks.
// cp.async double-buffered smem; mma.sync.m16n8k8.tf32.
// Epilogue scatters into g_M[o][i][k] (o=c>>3, k=c&7).
// Also fuses the x -> out[:, :512] copy.
// ---------------------------------------------------------------------------
#define AS_STR 36   // floats; bank = (4*m + k) % 32 for frag reads -> conflict-free
#define BS_STR 36

__device__ __forceinline__ uint32_t f2tf32(float f) {
    uint32_t u;
    asm("cvt.rna.tf32.f32 %0, %1;" : "=r"(u) : "f"(f));
    return u;
}
__device__ __forceinline__ void mma_tf32(float& d0, float& d1, float& d2, float& d3,
                                         uint32_t a0, uint32_t a1, uint32_t a2, uint32_t a3,
                                         uint32_t b0, uint32_t b1) {
    asm volatile(
        "mma.sync.aligned.m16n8k8.row.col.f32.tf32.tf32.f32 "
        "{%0,%1,%2,%3}, {%4,%5,%6,%7}, {%8,%9}, {%0,%1,%2,%3};"
        : "+f"(d0), "+f"(d1), "+f"(d2), "+f"(d3)
        : "r"(a0), "r"(a1), "r"(a2), "r"(a3), "r"(b0), "r"(b1));
}
__device__ __forceinline__ void cp16(uint32_t dst_smem, const void* src) {
    asm volatile("cp.async.ca.shared.global [%0], [%1], 16;" :: "r"(dst_smem), "l"(src));
}

__global__ void __launch_bounds__(128) gemm_kernel(
        const float* __restrict__ A, const float* __restrict__ Bm,
        float* __restrict__ out) {
    __shared__ float As[2][64][AS_STR];
    __shared__ float Bs[2][32][BS_STR];

    const int tid = threadIdx.x;
    const int lane = tid & 31;
    const int warp = tid >> 5;
    const int rowBase = blockIdx.y * 64;
    const int colBase = blockIdx.x * 32;

    // Fused copy: x (65536 float4) spread over 16384 threads, 4 each.
    {
        const int gt = (blockIdx.y * 16 + blockIdx.x) * 128 + tid;
        #pragma unroll
        for (int t = 0; t < 4; t++) {
            int f = gt + t * 16384;
            int row = f >> 7, col = (f & 127) * 4;
            *(float4*)(out + row * ROWW + col) = *(const float4*)(A + row * INF + col);
        }
    }

    // cp.async staging addresses
    const uint32_t asBase = (uint32_t)__cvta_generic_to_shared(&As[0][0][0]);
    const uint32_t bsBase = (uint32_t)__cvta_generic_to_shared(&Bs[0][0][0]);

    auto load_chunk = [&](int kt, int buf) {
        // A tile: 64 rows x 32 k -> 512 x 16B, 4 per thread (straight copy, no transpose)
        #pragma unroll
        for (int l = 0; l < 4; l++) {
            int f = tid + l * 128;
            int r = f >> 3, seg = f & 7;
            cp16(asBase + ((buf * 64 + r) * AS_STR + seg * 4) * 4,
                 &A[(rowBase + r) * INF + kt + seg * 4]);
        }
        // B tile: 32 k x 32 n -> 256 x 16B, 2 per thread
        #pragma unroll
        for (int l = 0; l < 2; l++) {
            int f = tid + l * 128;
            int kr = f >> 3, seg = f & 7;
            cp16(bsBase + ((buf * 32 + kr) * BS_STR + seg * 4) * 4,
                 &Bm[(kt + kr) * INF + colBase + seg * 4]);
        }
        asm volatile("cp.async.commit_group;");
    };

    float acc[4][4] = {};   // 4 n-frags x {c0..c3}
    const int warpM = warp * 16;
    const int g  = lane >> 2;   // groupID
    const int tg = lane & 3;    // threadID_in_group

    load_chunk(0, 0);

    int buf = 0;
    for (int t = 0; t < 16; t++) {
        if (t < 15) {
            load_chunk((t + 1) * 32, buf ^ 1);
            asm volatile("cp.async.wait_group 1;");
        } else {
            asm volatile("cp.async.wait_group 0;");
        }
        __syncthreads();

        #pragma unroll
        for (int ks = 0; ks < 4; ks++) {
            const int klo = ks * 8 + tg;
            const int khi = klo + 4;
            uint32_t a0 = f2tf32(As[buf][warpM + g    ][klo]);
            uint32_t a1 = f2tf32(As[buf][warpM + g + 8][klo]);
            uint32_t a2 = f2tf32(As[buf][warpM + g    ][khi]);
            uint32_t a3 = f2tf32(As[buf][warpM + g + 8][khi]);
            #pragma unroll
            for (int f = 0; f < 4; f++) {
                uint32_t b0 = f2tf32(Bs[buf][klo][f * 8 + g]);
                uint32_t b1 = f2tf32(Bs[buf][khi][f * 8 + g]);
                mma_tf32(acc[f][0], acc[f][1], acc[f][2], acc[f][3],
                         a0, a1, a2, a3, b0, b1);
            }
        }
        __syncthreads();
        buf ^= 1;
    }

    // Epilogue: scatter to g_M[o][i][k]
    #pragma unroll
    for (int f = 0; f < 4; f++) {
        const int col0 = colBase + f * 8 + tg * 2;
        const int row0 = rowBase + warpM + g;
        #pragma unroll
        for (int q = 0; q < 4; q++) {
            int row = row0 + (q >> 1) * 8;
            int col = col0 + (q & 1);
            g_M[(((col >> 3) * BATCH) + row) * KDIM + (col & 7)] = acc[f][q];
        }
    }
}

// ---------------------------------------------------------------------------
// Per-o: row sums, bitonic sort by sum (ascending), gather slab into sorted
// order. grid = 64 (one block per o), 512 threads.
// ---------------------------------------------------------------------------
__global__ void sort_kernel() {
    __shared__ float key[BATCH];
    __shared__ int   idx[BATCH];
    const int o = blockIdx.x;
    const int tid = threadIdx.x;
    const float4* Mo = (const float4*)&g_M[o * BATCH * KDIM];

    float4 r0 = Mo[tid * 2], r1 = Mo[tid * 2 + 1];
    key[tid] = (r0.x + r0.y) + (r0.z + r0.w) + (r1.x + r1.y) + (r1.z + r1.w);
    idx[tid] = tid;
    __syncthreads();

    for (int k = 2; k <= BATCH; k <<= 1) {
        for (int j = k >> 1; j > 0; j >>= 1) {
            int ixj = tid ^ j;
            if (ixj > tid) {
                bool up = (tid & k) == 0;
                float ka = key[tid], kb = key[ixj];
                if ((ka > kb) == up) {
                    key[tid] = kb; key[ixj] = ka;
                    int t = idx[tid]; idx[tid] = idx[ixj]; idx[ixj] = t;
                }
            }
            __syncthreads();
        }
    }

    g_s[o * BATCH + tid]    = key[tid];
    g_perm[o * BATCH + tid] = idx[tid];

    const int p = idx[tid];
    float4* Mso = (float4*)&g_Ms[o * BATCH * KDIM];
    Mso[tid * 2]     = Mo[p * 2];
    Mso[tid * 2 + 1] = Mo[p * 2 + 1];
}

// ---------------------------------------------------------------------------
// Pairwise with warp-uniform pruning window.
// grid (64 o, 4 chunks) x 128 threads: thread -> one sorted-i.
// ---------------------------------------------------------------------------
__global__ void pairwise_kernel(float* __restrict__ out) {
    __shared__ float4 sm[BATCH * 2];   // sorted slab, 16KB
    __shared__ float  sk[BATCH];       // sorted sums, 2KB
    const int o = blockIdx.x;
    const int tid = threadIdx.x;

    const float4* Ms = (const float4*)&g_Ms[o * BATCH * KDIM];
    for (int t = tid; t < BATCH * 2; t += 128) sm[t] = Ms[t];
    for (int t = tid; t < BATCH; t += 128)     sk[t] = g_s[o * BATCH + t];
    __syncthreads();

    const int i = blockIdx.y * 128 + tid;
    const float4 a0 = sm[i * 2 + 0];
    const float4 a1 = sm[i * 2 + 1];

    const int wbase = i & ~31;
    const float lo = sk[wbase]      - PRUNE_T;
    const float hi = sk[wbase + 31] + PRUNE_T;
    int jlo, jhi;
    { int l = 0, r = BATCH; while (l < r) { int m = (l + r) >> 1; if (sk[m] <  lo) l = m + 1; else r = m; } jlo = l; }
    { int l = 0, r = BATCH; while (l < r) { int m = (l + r) >> 1; if (sk[m] <= hi) l = m + 1; else r = m; } jhi = l; }

    float s = 0.f;
    #pragma unroll 2
    for (int j = jlo; j < jhi; j++) {
        float4 b0 = sm[j * 2 + 0];
        float4 b1 = sm[j * 2 + 1];
        float d = ( (fabsf(a0.x - b0.x) + fabsf(a0.y - b0.y))
                  + (fabsf(a0.z - b0.z) + fabsf(a0.w - b0.w)) )
                + ( (fabsf(a1.x - b1.x) + fabsf(a1.y - b1.y))
                  + (fabsf(a1.z - b1.z) + fabsf(a1.w - b1.w)) );
        s += __expf(-d);
    }

    const int oi = g_perm[o * BATCH + i];
    out[oi * ROWW + INF + o] = s;
}

extern "C" void kernel_launch(void* const* d_in, const int* in_sizes, int n_in,
                              void* d_out, int out_size) {
    const float* x = (const float*)d_in[0];   // [512, 512]
    const float* T = (const float*)d_in[1];   // [512, 64, 8] == [512, 512]
    float* out = (float*)d_out;               // [512, 576]

    gemm_kernel<<<dim3(16, 8), 128>>>(x, T, out);
    sort_kernel<<<OUTF, BATCH>>>();
    pairwise_kernel<<<dim3(OUTF, 4), 128>>>(out);
}

// round 5
// speedup vs baseline: 1.6749x; 1.1322x over previous
#include <cuda_runtime.h>
#include <cstdint>

#define BATCH 512
#define INF   512
#define OUTF  64
#define KDIM  8
#define ROWW  (INF + OUTF)   // 576
#define PRUNE_T 16.0f        // skipped pairs have d > 16 -> each < 1.1e-7, total < 5.7e-5

// Scratch (device global: no allocation).
__device__ float g_M[OUTF * BATCH * KDIM];   // [o][i][k], GEMM output

// ---------------------------------------------------------------------------
// tf32 tensor-core GEMM with split-K x2.
// C[i][c] = sum_in x[i][in] * T[in][c]; scatter to g_M[o][i][k] (o=c>>3,k=c&7).
// BM=64, BN=32, BK=16; 256 threads (8 warps); warps 0-3: K [0,256),
// warps 4-7: K [256,512); smem reduce. Double-buffered cp.async.
// No cvt: raw fp32 bits fed to tf32 MMA (HW-truncated; error cancels in the
// self term and all cross terms underflow).  Fuses the x -> out copy.
// ---------------------------------------------------------------------------
#define AS_STR 20   // bank(20*g + tg) all-distinct for frag reads
#define BS_STR 36

__device__ __forceinline__ void mma_tf32(float& d0, float& d1, float& d2, float& d3,
                                         uint32_t a0, uint32_t a1, uint32_t a2, uint32_t a3,
                                         uint32_t b0, uint32_t b1) {
    asm volatile(
        "mma.sync.aligned.m16n8k8.row.col.f32.tf32.tf32.f32 "
        "{%0,%1,%2,%3}, {%4,%5,%6,%7}, {%8,%9}, {%0,%1,%2,%3};"
        : "+f"(d0), "+f"(d1), "+f"(d2), "+f"(d3)
        : "r"(a0), "r"(a1), "r"(a2), "r"(a3), "r"(b0), "r"(b1));
}
__device__ __forceinline__ void cp16(uint32_t dst_smem, const void* src) {
    asm volatile("cp.async.ca.shared.global [%0], [%1], 16;" :: "r"(dst_smem), "l"(src));
}

__global__ void __launch_bounds__(256) gemm_kernel(
        const float* __restrict__ A, const float* __restrict__ Bm,
        float* __restrict__ out) {
    __shared__ float As[2][2][64][AS_STR];   // [buf][khalf][row][k]
    __shared__ float Bs[2][2][16][BS_STR];   // [buf][khalf][k][n]
    __shared__ float Cred[64][33];

    const int tid  = threadIdx.x;
    const int lane = tid & 31;
    const int warp = tid >> 5;
    const int h    = tid >> 7;          // k-half (loads AND compute: warp>>2 == tid>>7)
    const int tl   = tid & 127;         // lane within loader group
    const int rowBase = blockIdx.y * 64;
    const int colBase = blockIdx.x * 32;

    // Fused copy: x (65536 float4) over 32768 threads, 2 each.
    {
        const int gt = (blockIdx.y * 16 + blockIdx.x) * 256 + tid;
        #pragma unroll
        for (int t = 0; t < 2; t++) {
            int f = gt + t * 32768;
            int row = f >> 7, col = (f & 127) * 4;
            *(float4*)(out + row * ROWW + col) = *(const float4*)(A + row * INF + col);
        }
    }

    const uint32_t asBase = (uint32_t)__cvta_generic_to_shared(&As[0][0][0][0]);
    const uint32_t bsBase = (uint32_t)__cvta_generic_to_shared(&Bs[0][0][0][0]);

    auto load_chunk = [&](int t, int buf) {
        const int koff = h * 256 + t * 16;
        // A tile: 64 rows x 16 k = 256 float4, 2 per loader thread
        #pragma unroll
        for (int l = 0; l < 2; l++) {
            int f = tl + l * 128;
            int r = f >> 2, seg = f & 3;
            cp16(asBase + (((buf * 2 + h) * 64 + r) * AS_STR + seg * 4) * 4,
                 &A[(rowBase + r) * INF + koff + seg * 4]);
        }
        // B tile: 16 k x 32 n = 128 float4, 1 per loader thread
        {
            int kr = tl >> 3, seg = tl & 7;
            cp16(bsBase + (((buf * 2 + h) * 16 + kr) * BS_STR + seg * 4) * 4,
                 &Bm[(koff + kr) * INF + colBase + seg * 4]);
        }
        asm volatile("cp.async.commit_group;");
    };

    float acc[4][4] = {};
    const int warpM = (warp & 3) * 16;
    const int g  = lane >> 2;
    const int tg = lane & 3;

    load_chunk(0, 0);

    int buf = 0;
    for (int t = 0; t < 16; t++) {
        if (t < 15) {
            load_chunk(t + 1, buf ^ 1);
            asm volatile("cp.async.wait_group 1;");
        } else {
            asm volatile("cp.async.wait_group 0;");
        }
        __syncthreads();

        #pragma unroll
        for (int ks = 0; ks < 2; ks++) {
            const int klo = ks * 8 + tg;
            const int khi = klo + 4;
            uint32_t a0 = __float_as_uint(As[buf][h][warpM + g    ][klo]);
            uint32_t a1 = __float_as_uint(As[buf][h][warpM + g + 8][klo]);
            uint32_t a2 = __float_as_uint(As[buf][h][warpM + g    ][khi]);
            uint32_t a3 = __float_as_uint(As[buf][h][warpM + g + 8][khi]);
            #pragma unroll
            for (int f = 0; f < 4; f++) {
                uint32_t b0 = __float_as_uint(Bs[buf][h][klo][f * 8 + g]);
                uint32_t b1 = __float_as_uint(Bs[buf][h][khi][f * 8 + g]);
                mma_tf32(acc[f][0], acc[f][1], acc[f][2], acc[f][3],
                         a0, a1, a2, a3, b0, b1);
            }
        }
        __syncthreads();
        buf ^= 1;
    }

    // Split-K reduce: half 1 stages to smem, half 0 adds + scatters.
    if (h == 1) {
        #pragma unroll
        for (int f = 0; f < 4; f++)
            #pragma unroll
            for (int q = 0; q < 4; q++)
                Cred[warpM + g + (q >> 1) * 8][f * 8 + tg * 2 + (q & 1)] = acc[f][q];
    }
    __syncthreads();
    if (h == 0) {
        #pragma unroll
        for (int f = 0; f < 4; f++) {
            #pragma unroll
            for (int q = 0; q < 4; q++) {
                int lr = warpM + g + (q >> 1) * 8;
                int lc = f * 8 + tg * 2 + (q & 1);
                float v = acc[f][q] + Cred[lr][lc];
                int row = rowBase + lr;
                int col = colBase + lc;
                g_M[(((col >> 3) * BATCH) + row) * KDIM + (col & 7)] = v;
            }
        }
    }
}

// ---------------------------------------------------------------------------
// Fused sort + pairwise. One block per output feature o, 512 threads.
// 1) row sums -> hybrid bitonic sort (shfl for j<32, smem for j>=32: 10
//    barrier steps instead of 45), 2) gather slab into sorted order in smem,
// 3) windowed pairwise: warp scans only sorted j with s_j within warp's
//    [min-T, max+T]; skipped terms each < e^-T (rigorous L1 lower bound).
// ---------------------------------------------------------------------------
#define SHFL_STEP(kk)                                                    \
    {                                                                    \
        float kp = __shfl_xor_sync(0xffffffffu, km, j);                  \
        int   ip = __shfl_xor_sync(0xffffffffu, im, j);                  \
        bool up = (tid & (kk)) == 0;                                     \
        bool keepmin = ((tid & j) == 0) == up;                           \
        bool take = keepmin ? (kp < km) : (kp > km);                     \
        if (take) { km = kp; im = ip; }                                  \
    }

__global__ void __launch_bounds__(512) sortpair_kernel(float* __restrict__ out) {
    __shared__ float4 sraw [BATCH * 2];   // 16KB raw slab
    __shared__ float4 ssort[BATCH * 2];   // 16KB sorted slab
    __shared__ float  skey [BATCH];
    __shared__ int    sidx [BATCH];

    const int o   = blockIdx.x;
    const int tid = threadIdx.x;

    const float4* Mo = (const float4*)&g_M[o * BATCH * KDIM];
    float4 r0 = Mo[tid * 2], r1 = Mo[tid * 2 + 1];
    sraw[tid * 2] = r0;  sraw[tid * 2 + 1] = r1;

    float km = (r0.x + r0.y) + (r0.z + r0.w) + (r1.x + r1.y) + (r1.z + r1.w);
    int   im = tid;

    // Phases k = 2..32: fully intra-warp (register shfl, no barriers).
    #pragma unroll
    for (int k = 2; k <= 32; k <<= 1)
        for (int j = k >> 1; j >= 1; j >>= 1)
            SHFL_STEP(k)

    // Phases k = 64..512: smem exchange for j>=32, shfl for the tail.
    for (int k = 64; k <= 512; k <<= 1) {
        skey[tid] = km; sidx[tid] = im;
        __syncthreads();
        for (int j = k >> 1; j >= 32; j >>= 1) {
            int p = tid ^ j;
            float kp = skey[p];  int ip = sidx[p];
            float kc = skey[tid]; int ic = sidx[tid]; (void)ic;
            __syncthreads();
            bool up = (tid & k) == 0;
            bool keepmin = ((tid & j) == 0) == up;
            bool take = keepmin ? (kp < kc) : (kp > kc);
            if (take) { skey[tid] = kp; sidx[tid] = ip; }
            __syncthreads();
        }
        km = skey[tid]; im = sidx[tid];
        for (int j = 16; j >= 1; j >>= 1)
            SHFL_STEP(k)
    }

    // Publish sorted keys; gather slab into sorted order.
    skey[tid] = km;
    ssort[tid * 2]     = sraw[im * 2];
    ssort[tid * 2 + 1] = sraw[im * 2 + 1];
    __syncthreads();

    const float4 a0 = ssort[tid * 2 + 0];
    const float4 a1 = ssort[tid * 2 + 1];

    const int wbase = tid & ~31;
    const float lo = skey[wbase]      - PRUNE_T;
    const float hi = skey[wbase + 31] + PRUNE_T;
    int jlo, jhi;
    { int l = 0, r = BATCH; while (l < r) { int m = (l + r) >> 1; if (skey[m] <  lo) l = m + 1; else r = m; } jlo = l; }
    { int l = 0, r = BATCH; while (l < r) { int m = (l + r) >> 1; if (skey[m] <= hi) l = m + 1; else r = m; } jhi = l; }

    float s0 = 0.f, s1 = 0.f;
    int j = jlo;
    for (; j + 1 < jhi; j += 2) {
        {
            float4 b0 = ssort[j * 2 + 0];
            float4 b1 = ssort[j * 2 + 1];
            float d = ( (fabsf(a0.x - b0.x) + fabsf(a0.y - b0.y))
                      + (fabsf(a0.z - b0.z) + fabsf(a0.w - b0.w)) )
                    + ( (fabsf(a1.x - b1.x) + fabsf(a1.y - b1.y))
                      + (fabsf(a1.z - b1.z) + fabsf(a1.w - b1.w)) );
            s0 += __expf(-d);
        }
        {
            float4 b0 = ssort[(j + 1) * 2 + 0];
            float4 b1 = ssort[(j + 1) * 2 + 1];
            float d = ( (fabsf(a0.x - b0.x) + fabsf(a0.y - b0.y))
                      + (fabsf(a0.z - b0.z) + fabsf(a0.w - b0.w)) )
                    + ( (fabsf(a1.x - b1.x) + fabsf(a1.y - b1.y))
                      + (fabsf(a1.z - b1.z) + fabsf(a1.w - b1.w)) );
            s1 += __expf(-d);
        }
    }
    if (j < jhi) {
        float4 b0 = ssort[j * 2 + 0];
        float4 b1 = ssort[j * 2 + 1];
        float d = ( (fabsf(a0.x - b0.x) + fabsf(a0.y - b0.y))
                  + (fabsf(a0.z - b0.z) + fabsf(a0.w - b0.w)) )
                + ( (fabsf(a1.x - b1.x) + fabsf(a1.y - b1.y))
                  + (fabsf(a1.z - b1.z) + fabsf(a1.w - b1.w)) );
        s0 += __expf(-d);
    }

    out[im * ROWW + INF + o] = s0 + s1;
}

extern "C" void kernel_launch(void* const* d_in, const int* in_sizes, int n_in,
                              void* d_out, int out_size) {
    const float* x = (const float*)d_in[0];   // [512, 512]
    const float* T = (const float*)d_in[1];   // [512, 64, 8] == [512, 512]
    float* out = (float*)d_out;               // [512, 576]

    gemm_kernel<<<dim3(16, 8), 256>>>(x, T, out);
    sortpair_kernel<<<OUTF, 512>>>(out);
}